// round 15
// baseline (speedup 1.0000x reference)
#include <cuda_runtime.h>

typedef unsigned long long ULL;

// Problem constants: B=8192, T=100, D=16, H=32, Hd=50
#define NB 8192
#define NT 100
#define ND 16
#define NH 32
#define NHD 50
#define NEUL 10

#define NTHREADS 256          // 8 warps: 4 h-warps (chain) + 4 y-warps (dy)
#define EPB 64                // elements per block
#define NBLOCKS (NB/EPB)      // 128 -> 1 block per SM
#define E 4                   // elements per 8-lane group (both warp classes)

// Weight strides (floats): role bases hit 8 distinct bank quads; rows 16B-aligned.
#define W1S 36                // W1 h-part: 56 rows x 32 cols (rows 50..55 zero)
#define W2S 52                // W2: 32 rows x 52 cols (cols 50,51 zero)
#define W3S 36                // W3: 64 rows x 32 cols
// Activation strides: ==2 (mod 4) -> 8B loads, 4 groups spread across bank quads at E=4.
#define HS  34
#define Z1S 58

// Dynamic smem layout (float offsets)
#define OFF_W1 0
#define OFF_W2 (OFF_W1 + 56*W1S)        // 2016
#define OFF_W3 (OFF_W2 + NH*W2S)        // +1664
#define OFF_H0 (OFF_W3 + 2*NH*W3S)      // +2304
#define OFF_H1 (OFF_H0 + EPB*HS)        // +2176
#define OFF_Z  (OFF_H1 + EPB*HS)        // +2176
#define OFF_B2 (OFF_Z  + EPB*Z1S)       // +3712
#define OFF_B3 (OFF_B2 + NH)
#define OFF_W4 (OFF_B3 + 2*NH)
#define SMEM_FLOATS (OFF_W4 + 2*NH)     // 14208 floats
#define SMEM_BYTES (SMEM_FLOATS * 4)    // 56832 B (needs dynamic smem)

__device__ __forceinline__ ULL ffma2(ULL a, ULL b, ULL c) {
    ULL d;
    asm("fma.rn.f32x2 %0, %1, %2, %3;" : "=l"(d) : "l"(a), "l"(b), "l"(c));
    return d;
}
__device__ __forceinline__ float sum2(ULL v) {
    return __uint_as_float((unsigned)v) + __uint_as_float((unsigned)(v >> 32));
}
__device__ __forceinline__ float fast_tanh(float v) {
    float r;
    asm("tanh.approx.f32 %0, %1;" : "=f"(r) : "f"(v));
    return r;
}

__global__ __launch_bounds__(NTHREADS, 1) void latentode_kernel(
    const float* __restrict__ g_dt, const float* __restrict__ g_x,
    const float* __restrict__ g_W1, const float* __restrict__ g_b1,
    const float* __restrict__ g_W2, const float* __restrict__ g_b2,
    const float* __restrict__ g_W3, const float* __restrict__ g_b3,
    const float* __restrict__ g_W4, const float* __restrict__ g_b4,
    float* __restrict__ g_out)
{
    extern __shared__ float smem[];
    float* W1s = smem + OFF_W1;
    float* W2s = smem + OFF_W2;
    float* W3s = smem + OFF_W3;
    float* z1s = smem + OFF_Z;
    float* b2s = smem + OFF_B2;
    float* b3s = smem + OFF_B3;
    float* w4s = smem + OFF_W4;

    const int tid  = threadIdx.x;
    const int wid  = tid >> 5;
    const bool isy = (wid >= 4);          // y-warps: dy path; h-warps: ODE chain
    const int hw   = wid & 3;             // warp index within class
    const int r    = tid & 7;             // role in 8-lane group
    const int g8   = (tid >> 3) & 3;      // group within warp
    const int elb  = hw * 16 + g8 * E;    // first element of this group's 4
    const int b0   = blockIdx.x * EPB + elb;

    // ---- stage weights (zero-padded) + biases ----
    for (int i = tid; i < 56 * W1S; i += NTHREADS) {
        int row = i / W1S, col = i - row * W1S;
        W1s[i] = (row < NHD && col < NH) ? g_W1[row * (ND + NH) + ND + col] : 0.0f;
    }
    for (int i = tid; i < NH * W2S; i += NTHREADS) {
        int row = i / W2S, col = i - row * W2S;
        W2s[i] = (col < NHD) ? g_W2[row * NHD + col] : 0.0f;
    }
    for (int i = tid; i < 2 * NH * W3S; i += NTHREADS) {
        int row = i / W3S, col = i - row * W3S;
        W3s[i] = (col < NH) ? g_W3[row * NH + col] : 0.0f;
    }
    if (tid < NH)     b2s[tid] = g_b2[tid];
    if (tid < 2 * NH) { b3s[tid] = g_b3[tid]; w4s[tid] = g_W4[tid]; }
    for (int i = tid; i < EPB * Z1S; i += NTHREADS) z1s[i] = 0.0f;
    for (int i = tid; i < EPB * HS;  i += NTHREADS) { smem[OFF_H0 + i] = 0.0f; smem[OFF_H1 + i] = 0.0f; }
    const float b4v = g_b4[0];

    float h_own[4][E];                    // h-warps: owned h rows per element
#pragma unroll
    for (int j = 0; j < 4; j++)
#pragma unroll
        for (int e = 0; e < E; e++) h_own[j][e] = 0.0f;

    __syncthreads();

#pragma unroll 1
    for (int t = 0; t < NT; t++) {
        // ---- per-timestep prep ----
        float sc[E];
#pragma unroll
        for (int e = 0; e < E; e++) {
            float2 dv = *(const float2*)(g_dt + ((size_t)(b0 + e)) * NT * 2 + (size_t)t * 2);
            sc[e] = (dv.y - dv.x) * (0.1f / 24.0f);   // STEP * DT_SCALER folded
        }
        float x0[E], p1[7][E], dyacc[E];
        if (isy) {
#pragma unroll
            for (int e = 0; e < E; e++) {
                x0[e] = g_x[((size_t)(b0 + e)) * NT * ND + (size_t)t * ND];
                dyacc[e] = 0.0f;
            }
        } else {
            // p1 = b1 + x @ W1x^T  (element-at-a-time, L1-hot W1 x-part)
#pragma unroll 1
            for (int e = 0; e < E; e++) {
                const float4* xv = (const float4*)(g_x + ((size_t)(b0 + e)) * NT * ND + (size_t)t * ND);
                float4 xa = xv[0], xb = xv[1], xc = xv[2], xd = xv[3];
#pragma unroll
                for (int j = 0; j < 7; j++) {
                    int row = r + 8 * j;
                    if (row < NHD) {
                        const float4* wp = (const float4*)(g_W1 + row * (ND + NH));
                        float4 w0 = wp[0], w1 = wp[1], w2 = wp[2], w3 = wp[3];
                        float acc = g_b1[row];
                        acc = fmaf(w0.x, xa.x, acc); acc = fmaf(w0.y, xa.y, acc);
                        acc = fmaf(w0.z, xa.z, acc); acc = fmaf(w0.w, xa.w, acc);
                        acc = fmaf(w1.x, xb.x, acc); acc = fmaf(w1.y, xb.y, acc);
                        acc = fmaf(w1.z, xb.z, acc); acc = fmaf(w1.w, xb.w, acc);
                        acc = fmaf(w2.x, xc.x, acc); acc = fmaf(w2.y, xc.y, acc);
                        acc = fmaf(w2.z, xc.z, acc); acc = fmaf(w2.w, xc.w, acc);
                        acc = fmaf(w3.x, xd.x, acc); acc = fmaf(w3.y, xd.y, acc);
                        acc = fmaf(w3.z, xd.z, acc); acc = fmaf(w3.w, xd.w, acc);
                        p1[j][e] = acc;
                    } else p1[j][e] = 0.0f;           // pad rows -> z1 = tanh(0) = 0
                }
            }
        }

#pragma unroll 1
        for (int it = 0; it < NEUL; it++) {
            const float* hb = smem + ((it & 1) ? OFF_H1 : OFF_H0) + elb * HS;  // read buffer
            float*       hn = smem + ((it & 1) ? OFF_H0 : OFF_H1);             // write buffer

            if (isy) {
                // ===== dy path: two 4-row W3 chunks =====
#pragma unroll 1
                for (int c = 0; c < 2; c++) {
                    ULL a[4][E];
#pragma unroll
                    for (int jj = 0; jj < 4; jj++)
#pragma unroll
                        for (int e = 0; e < E; e++) a[jj][e] = 0ULL;
                    const float* w3 = W3s + (r + 32 * c) * W3S;
#pragma unroll
                    for (int kp = 0; kp < 8; kp++) {
                        ULL h0[E], h1[E];
#pragma unroll
                        for (int e = 0; e < E; e++) {
                            const ULL* p = (const ULL*)(hb + e * HS + 4 * kp);
                            h0[e] = p[0]; h1[e] = p[1];
                        }
#pragma unroll
                        for (int jj = 0; jj < 4; jj++) {
                            ulonglong2 w = *(const ulonglong2*)(w3 + jj * 8 * W3S + 4 * kp);
#pragma unroll
                            for (int e = 0; e < E; e++) {
                                a[jj][e] = ffma2(w.x, h0[e], a[jj][e]);
                                a[jj][e] = ffma2(w.y, h1[e], a[jj][e]);
                            }
                        }
                    }
#pragma unroll
                    for (int jj = 0; jj < 4; jj++) {
                        float b3v = b3s[32 * c + r + 8 * jj], w4v = w4s[32 * c + r + 8 * jj];
#pragma unroll
                        for (int e = 0; e < E; e++)
                            dyacc[e] = fmaf(w4v, fast_tanh(sum2(a[jj][e]) + b3v), dyacc[e]);
                    }
                }
            } else {
                // ===== chain: W1h (4+3 rows) -> z1 =====
                {
                    ULL a[4][E];
#pragma unroll
                    for (int jj = 0; jj < 4; jj++)
#pragma unroll
                        for (int e = 0; e < E; e++) a[jj][e] = 0ULL;
                    const float* w1 = W1s + r * W1S;
#pragma unroll
                    for (int kp = 0; kp < 8; kp++) {
                        ULL h0[E], h1[E];
#pragma unroll
                        for (int e = 0; e < E; e++) {
                            const ULL* p = (const ULL*)(hb + e * HS + 4 * kp);
                            h0[e] = p[0]; h1[e] = p[1];
                        }
#pragma unroll
                        for (int jj = 0; jj < 4; jj++) {
                            ulonglong2 w = *(const ulonglong2*)(w1 + jj * 8 * W1S + 4 * kp);
#pragma unroll
                            for (int e = 0; e < E; e++) {
                                a[jj][e] = ffma2(w.x, h0[e], a[jj][e]);
                                a[jj][e] = ffma2(w.y, h1[e], a[jj][e]);
                            }
                        }
                    }
#pragma unroll
                    for (int jj = 0; jj < 4; jj++)
#pragma unroll
                        for (int e = 0; e < E; e++)
                            z1s[(elb + e) * Z1S + r + 8 * jj] = fast_tanh(sum2(a[jj][e]) + p1[jj][e]);
                }
                {
                    ULL a[3][E];
#pragma unroll
                    for (int jj = 0; jj < 3; jj++)
#pragma unroll
                        for (int e = 0; e < E; e++) a[jj][e] = 0ULL;
                    const float* w1 = W1s + (r + 32) * W1S;
#pragma unroll
                    for (int kp = 0; kp < 8; kp++) {
                        ULL h0[E], h1[E];
#pragma unroll
                        for (int e = 0; e < E; e++) {
                            const ULL* p = (const ULL*)(hb + e * HS + 4 * kp);
                            h0[e] = p[0]; h1[e] = p[1];
                        }
#pragma unroll
                        for (int jj = 0; jj < 3; jj++) {
                            ulonglong2 w = *(const ulonglong2*)(w1 + jj * 8 * W1S + 4 * kp);
#pragma unroll
                            for (int e = 0; e < E; e++) {
                                a[jj][e] = ffma2(w.x, h0[e], a[jj][e]);
                                a[jj][e] = ffma2(w.y, h1[e], a[jj][e]);
                            }
                        }
                    }
#pragma unroll
                    for (int jj = 0; jj < 3; jj++)
#pragma unroll
                        for (int e = 0; e < E; e++)   // rows 50..55 get tanh(0)=0
                            z1s[(elb + e) * Z1S + r + 8 * (4 + jj)] = fast_tanh(sum2(a[jj][e]) + p1[4 + jj][e]);
                }
                __syncwarp();

                // ===== chain: W2 -> h(next) =====
                {
                    ULL a[4][E];
#pragma unroll
                    for (int jj = 0; jj < 4; jj++)
#pragma unroll
                        for (int e = 0; e < E; e++) a[jj][e] = 0ULL;
                    const float* w2 = W2s + r * W2S;
                    const float* zb = z1s + elb * Z1S;
#pragma unroll
                    for (int kp = 0; kp < 13; kp++) {
                        ULL z0[E], z1v[E];
#pragma unroll
                        for (int e = 0; e < E; e++) {
                            const ULL* p = (const ULL*)(zb + e * Z1S + 4 * kp);
                            z0[e] = p[0]; z1v[e] = p[1];
                        }
#pragma unroll
                        for (int jj = 0; jj < 4; jj++) {
                            ulonglong2 w = *(const ulonglong2*)(w2 + jj * 8 * W2S + 4 * kp);
#pragma unroll
                            for (int e = 0; e < E; e++) {
                                a[jj][e] = ffma2(w.x, z0[e], a[jj][e]);
                                a[jj][e] = ffma2(w.y, z1v[e], a[jj][e]);
                            }
                        }
                    }
#pragma unroll
                    for (int jj = 0; jj < 4; jj++) {
                        int row = r + 8 * jj;
                        float b2v = b2s[row];
#pragma unroll
                        for (int e = 0; e < E; e++) {
                            h_own[jj][e] = fmaf(sc[e], fast_tanh(sum2(a[jj][e]) + b2v), h_own[jj][e]);
                            hn[(elb + e) * HS + row] = h_own[jj][e];
                        }
                    }
                }
            }
            __syncthreads();   // orders y-reads(buf p) before h-writes(buf p) of next iter
        }

        if (isy) {
#pragma unroll
            for (int e = 0; e < E; e++) {
                float red = dyacc[e];
                red += __shfl_xor_sync(0xffffffffu, red, 1);
                red += __shfl_xor_sync(0xffffffffu, red, 2);
                red += __shfl_xor_sync(0xffffffffu, red, 4);
                if (r == 0)
                    g_out[((size_t)(b0 + e)) * NT + t] =
                        fmaf(sc[e], red + 10.0f * b4v, x0[e]);
            }
        }
        // NEUL even -> h ends in buffer H0, matching next timestep's it=0 read
    }
}

extern "C" void kernel_launch(void* const* d_in, const int* in_sizes, int n_in,
                              void* d_out, int out_size) {
    cudaFuncSetAttribute(latentode_kernel,
                         cudaFuncAttributeMaxDynamicSharedMemorySize, SMEM_BYTES);
    latentode_kernel<<<NBLOCKS, NTHREADS, SMEM_BYTES>>>(
        (const float*)d_in[0],  // dt (8192,100,2)
        (const float*)d_in[1],  // x  (8192,100,16)
        (const float*)d_in[2],  // W1 (50,48)
        (const float*)d_in[3],  // b1 (50)
        (const float*)d_in[4],  // W2 (32,50)
        (const float*)d_in[5],  // b2 (32)
        (const float*)d_in[6],  // W3 (64,32)
        (const float*)d_in[7],  // b3 (64)
        (const float*)d_in[8],  // W4 (1,64)
        (const float*)d_in[9],  // b4 (1)
        (float*)d_out);         // out (8192,100) float32
}